// round 1
// baseline (speedup 1.0000x reference)
#include <cuda_runtime.h>

// Problem constants
#define NB 4
#define NP 1024
#define ND 512
#define NH 8
#define NDK 64

// Scratch (no allocations allowed)
__device__ float g_qp[NB * NP * ND];
__device__ float g_kp[NB * NP * ND];
__device__ float g_vp[NB * NP * ND];
__device__ float g_ct[NB * 2 * NP * ND];

// ---------------------------------------------------------------------------
// Tiled SGEMM body: C[M,512] = A[M,512] @ W[512,512] + bias, 128x128x8 tiles,
// 256 threads, 8x8 per-thread microtile.
// ---------------------------------------------------------------------------
__device__ __forceinline__ void gemm_body(const float* __restrict__ A,
                                          const float* __restrict__ W,
                                          const float* __restrict__ bias,
                                          float* __restrict__ C)
{
    __shared__ float As[8][128];
    __shared__ float Bs[8][128];
    const int tid  = threadIdx.x;
    const int brow = blockIdx.y * 128;
    const int bcol = blockIdx.x * 128;
    const int ty = tid >> 4, tx = tid & 15;

    float acc[8][8];
#pragma unroll
    for (int i = 0; i < 8; i++)
#pragma unroll
        for (int j = 0; j < 8; j++) acc[i][j] = 0.f;

    const int ar = tid >> 1, akq = (tid & 1) * 4;
    const int br = tid >> 5, bc = (tid & 31) * 4;

    for (int kt = 0; kt < 512; kt += 8) {
        float4 av = *(const float4*)(A + (size_t)(brow + ar) * 512 + kt + akq);
        As[akq + 0][ar] = av.x;
        As[akq + 1][ar] = av.y;
        As[akq + 2][ar] = av.z;
        As[akq + 3][ar] = av.w;
        *(float4*)&Bs[br][bc] = *(const float4*)(W + (size_t)(kt + br) * 512 + bcol + bc);
        __syncthreads();
#pragma unroll
        for (int k = 0; k < 8; k++) {
            float a[8], w[8];
            *(float4*)&a[0] = *(const float4*)&As[k][ty * 8];
            *(float4*)&a[4] = *(const float4*)&As[k][ty * 8 + 4];
            *(float4*)&w[0] = *(const float4*)&Bs[k][tx * 8];
            *(float4*)&w[4] = *(const float4*)&Bs[k][tx * 8 + 4];
#pragma unroll
            for (int i = 0; i < 8; i++)
#pragma unroll
                for (int j = 0; j < 8; j++) acc[i][j] += a[i] * w[j];
        }
        __syncthreads();
    }

#pragma unroll
    for (int i = 0; i < 8; i++) {
        const size_t row = (size_t)(brow + ty * 8 + i);
#pragma unroll
        for (int j = 0; j < 8; j += 4) {
            const int col = bcol + tx * 8 + j;
            float4 o;
            o.x = acc[i][j + 0] + bias[col + 0];
            o.y = acc[i][j + 1] + bias[col + 1];
            o.z = acc[i][j + 2] + bias[col + 2];
            o.w = acc[i][j + 3] + bias[col + 3];
            *(float4*)(C + row * 512 + col) = o;
        }
    }
}

// Projections: z=0 -> qp, z=1 -> kp, z=2 -> vp. Grid (4, 32, 3).
__global__ __launch_bounds__(256, 2)
void proj_gemm(const float* __restrict__ q, const float* __restrict__ k,
               const float* __restrict__ v,
               const float* __restrict__ Wq, const float* __restrict__ bq,
               const float* __restrict__ Wk, const float* __restrict__ bk,
               const float* __restrict__ Wv, const float* __restrict__ bv)
{
    if (blockIdx.z == 0)      gemm_body(q, Wq, bq, g_qp);
    else if (blockIdx.z == 1) gemm_body(k, Wk, bk, g_kp);
    else                      gemm_body(v, Wv, bv, g_vp);
}

// Output projection: Y[8192,512] = ct @ Wo + bo. Grid (4, 64, 1).
__global__ __launch_bounds__(256, 2)
void out_gemm(const float* __restrict__ Wo, const float* __restrict__ bo,
              float* __restrict__ out)
{
    gemm_body(g_ct, Wo, bo, out);
}

// ---------------------------------------------------------------------------
// Band attention, both directions, per CTA: one (b, h, 64-row chunk).
// Tile: 128 rows (chunk +/- 32) of q/k/v, 64 dims, smem stride 65 (bank-free).
// Computes s1[l][ds] = q[l].k[l+ds-32], s2[l][ds] = k[l].q[l+ds-32],
// softmaxes each row over the 65-wide band, accumulates out1/out2 into g_ct,
// and writes the FULL 1024-wide A1/A2 rows (zeros outside band) to d_out.
// ---------------------------------------------------------------------------
#define ATT_SMEM_FLOATS (3 * 128 * 65 + 2 * 64 * 65)
#define ATT_SMEM_BYTES  (ATT_SMEM_FLOATS * 4)

__global__ __launch_bounds__(256)
void attn_kernel(float* __restrict__ A1out, float* __restrict__ A2out)
{
    extern __shared__ float sm[];
    float* qs = sm;                 // [128][65]
    float* ks = qs + 128 * 65;      // [128][65]
    float* vs = ks + 128 * 65;      // [128][65]
    float* s1 = vs + 128 * 65;      // [64][65]
    float* s2 = s1 + 64 * 65;       // [64][65]

    const int tid = threadIdx.x;
    const int h = blockIdx.y, b = blockIdx.z;
    const int l0 = blockIdx.x * 64;

    // Load q/k/v tiles: rows l0-32 .. l0+95, zero-fill out-of-range rows.
    for (int i = tid; i < 128 * 16; i += 256) {
        const int r = i >> 4, d4 = (i & 15) * 4;
        const int rg = l0 - 32 + r;
        float4 q4 = make_float4(0.f, 0.f, 0.f, 0.f);
        float4 k4 = q4, v4 = q4;
        if (rg >= 0 && rg < 1024) {
            const size_t base = ((size_t)((b * 1024 + rg) * 8 + h)) * 64 + d4;
            q4 = *(const float4*)(g_qp + base);
            k4 = *(const float4*)(g_kp + base);
            v4 = *(const float4*)(g_vp + base);
        }
        const int o = r * 65 + d4;
        qs[o] = q4.x; qs[o + 1] = q4.y; qs[o + 2] = q4.z; qs[o + 3] = q4.w;
        ks[o] = k4.x; ks[o + 1] = k4.y; ks[o + 2] = k4.z; ks[o + 3] = k4.w;
        vs[o] = v4.x; vs[o + 1] = v4.y; vs[o + 2] = v4.z; vs[o + 3] = v4.w;
    }
    __syncthreads();

    // Band scores (both directions).
    for (int p = tid; p < 64 * 65; p += 256) {
        const int l = p / 65, ds = p - l * 65;
        const int sg = l0 + l + ds - 32;
        float sc1 = -1e30f, sc2 = -1e30f;
        if (sg >= 0 && sg < 1024) {
            const float* qr = qs + (l + 32) * 65;
            const float* kr = ks + (l + 32) * 65;
            const float* qc = qs + (l + ds) * 65;
            const float* kc = ks + (l + ds) * 65;
            float a = 0.f, c = 0.f;
#pragma unroll
            for (int e = 0; e < 64; e++) { a += qr[e] * kc[e]; c += kr[e] * qc[e]; }
            sc1 = 0.125f * a;   // scale = 1/sqrt(64)
            sc2 = 0.125f * c;
        }
        s1[p] = sc1;
        s2[p] = sc2;
    }
    __syncthreads();

    // Row softmax in-place: 128 tasks (64 rows x 2 matrices), warp per task.
    const int warp = tid >> 5, lane = tid & 31;
    for (int task = warp; task < 128; task += 8) {
        float* row = (task < 64) ? (s1 + task * 65) : (s2 + (task - 64) * 65);
        float m = -1e30f;
        for (int ds = lane; ds < 65; ds += 32) m = fmaxf(m, row[ds]);
#pragma unroll
        for (int o = 16; o > 0; o >>= 1) m = fmaxf(m, __shfl_xor_sync(0xffffffffu, m, o));
        float sum = 0.f;
        for (int ds = lane; ds < 65; ds += 32) {
            float pv = __expf(row[ds] - m);
            row[ds] = pv;
            sum += pv;
        }
#pragma unroll
        for (int o = 16; o > 0; o >>= 1) sum += __shfl_xor_sync(0xffffffffu, sum, o);
        const float inv = 1.f / sum;
        for (int ds = lane; ds < 65; ds += 32) row[ds] *= inv;
    }
    __syncthreads();

    // out1 = A1 @ v, out2 = A2 @ q -> concatenated buffer g_ct.
    const int d = tid & 63;
    for (int l = tid >> 6; l < 64; l += 4) {
        const float* a1 = s1 + l * 65;
        const float* a2 = s2 + l * 65;
        float acc1 = 0.f, acc2 = 0.f;
#pragma unroll
        for (int ds = 0; ds < 65; ds++) {
            const int c = (l + ds) * 65 + d;
            acc1 += a1[ds] * vs[c];
            acc2 += a2[ds] * qs[c];
        }
        const int lg = l0 + l;
        const size_t col = (size_t)h * 64 + d;
        g_ct[((size_t)b * 2048 + lg) * 512 + col]        = acc1;
        g_ct[((size_t)b * 2048 + 1024 + lg) * 512 + col] = acc2;
    }

    // Write full A1/A2 rows (1024 wide, zeros outside band). No sync needed:
    // only reads of s1/s2 since last barrier.
    const int s = tid * 4;
    for (int l = 0; l < 64; l++) {
        const int lg = l0 + l;
        const size_t base = (((size_t)(b * 8 + h)) * 1024 + lg) * 1024;
        float4 o1, o2;
        float* p1 = &o1.x;
        float* p2 = &o2.x;
#pragma unroll
        for (int j = 0; j < 4; j++) {
            const int ds = s + j - lg + 32;
            const bool in = (ds >= 0) && (ds <= 64);
            p1[j] = in ? s1[l * 65 + ds] : 0.f;
            p2[j] = in ? s2[l * 65 + ds] : 0.f;
        }
        *(float4*)(A1out + base + s) = o1;
        *(float4*)(A2out + base + s) = o2;
    }
}

// ---------------------------------------------------------------------------
extern "C" void kernel_launch(void* const* d_in, const int* in_sizes, int n_in,
                              void* d_out, int out_size)
{
    const float* queries = (const float*)d_in[0];
    const float* keys    = (const float*)d_in[1];
    const float* values  = (const float*)d_in[2];
    const float* Wq = (const float*)d_in[3];
    const float* bq = (const float*)d_in[4];
    const float* Wk = (const float*)d_in[5];
    const float* bk = (const float*)d_in[6];
    const float* Wv = (const float*)d_in[7];
    const float* bv = (const float*)d_in[8];
    const float* Wo = (const float*)d_in[9];
    const float* bo = (const float*)d_in[10];
    // d_in[11] = num_patches (int32, always 1024) -- shapes are fixed.

    float* out = (float*)d_out;                         // (4, 2048, 512)
    float* A1  = out + (size_t)4 * 2048 * 512;          // (4, 8, 1024, 1024)
    float* A2  = A1 + (size_t)4 * 8 * 1024 * 1024;      // (4, 8, 1024, 1024)

    cudaFuncSetAttribute(attn_kernel,
                         cudaFuncAttributeMaxDynamicSharedMemorySize,
                         ATT_SMEM_BYTES);

    // 1) Q/K/V projections (fused into one launch, z selects).
    proj_gemm<<<dim3(4, 32, 3), 256>>>(queries, keys, values,
                                       Wq, bq, Wk, bk, Wv, bv);

    // 2) Band attention both directions + full A1/A2 stores.
    attn_kernel<<<dim3(16, 8, 4), 256, ATT_SMEM_BYTES>>>(A1, A2);

    // 3) Output projection of the concatenated (out1|out2) buffer.
    out_gemm<<<dim3(4, 64, 1), 256>>>(Wo, bo, out);
}

// round 3
// speedup vs baseline: 1.5988x; 1.5988x over previous
#include <cuda_runtime.h>
#include <cuda_bf16.h>
#include <cstdint>
#include <cstring>

#define NB 4
#define NP 1024
#define ND 512
#define NH 8
#define NDK 64

// ---------------------------------------------------------------------------
// Scratch (device globals; no allocations allowed)
// ---------------------------------------------------------------------------
__device__ float g_qp[NB * NP * ND];
__device__ float g_kp[NB * NP * ND];
__device__ float g_vp[NB * NP * ND];
__device__ __align__(16) __nv_bfloat16 g_inh[3 * NB * NP * ND];   // q,k,v hi
__device__ __align__(16) __nv_bfloat16 g_inl[3 * NB * NP * ND];   // q,k,v lo
__device__ __align__(16) __nv_bfloat16 g_wth[4 * ND * ND];        // W^T hi (n,k)
__device__ __align__(16) __nv_bfloat16 g_wtl[4 * ND * ND];        // W^T lo
__device__ __align__(16) __nv_bfloat16 g_cth[NB * 2 * NP * ND];   // concat hi
__device__ __align__(16) __nv_bfloat16 g_ctl[NB * 2 * NP * ND];   // concat lo

// ---------------------------------------------------------------------------
// PTX helpers (sm_100 baseline: mma.sync + ldmatrix + cp.async)
// ---------------------------------------------------------------------------
__device__ __forceinline__ uint32_t smem_u32(const void* p) {
    uint32_t a;
    asm("{ .reg .u64 t; cvta.to.shared.u64 t, %1; cvt.u32.u64 %0, t; }"
        : "=r"(a) : "l"(p));
    return a;
}

#define CP_ASYNC16(dst, src) \
    asm volatile("cp.async.cg.shared.global [%0], [%1], 16;" \
                 :: "r"(dst), "l"(src) : "memory")
#define CP_COMMIT() asm volatile("cp.async.commit_group;" ::: "memory")
#define CP_WAIT(n)  asm volatile("cp.async.wait_group %0;" :: "n"(n) : "memory")

__device__ __forceinline__ void ldsm_x4(uint32_t* r, uint32_t addr) {
    asm volatile("ldmatrix.sync.aligned.m8n8.x4.shared.b16 {%0,%1,%2,%3}, [%4];"
                 : "=r"(r[0]), "=r"(r[1]), "=r"(r[2]), "=r"(r[3]) : "r"(addr));
}

__device__ __forceinline__ void mma_bf16(float* d, const uint32_t* a,
                                         const uint32_t* b) {
    asm volatile(
        "mma.sync.aligned.m16n8k16.row.col.f32.bf16.bf16.f32 "
        "{%0,%1,%2,%3}, {%4,%5,%6,%7}, {%8,%9}, {%0,%1,%2,%3};"
        : "+f"(d[0]), "+f"(d[1]), "+f"(d[2]), "+f"(d[3])
        : "r"(a[0]), "r"(a[1]), "r"(a[2]), "r"(a[3]), "r"(b[0]), "r"(b[1]));
}

__device__ __forceinline__ uint16_t bf_bits(__nv_bfloat16 a) {
    unsigned short s; memcpy(&s, &a, 2); return s;
}
__device__ __forceinline__ uint32_t pack2(__nv_bfloat16 a, __nv_bfloat16 b) {
    return (uint32_t)bf_bits(a) | ((uint32_t)bf_bits(b) << 16);
}
__device__ __forceinline__ void split1(float x, __nv_bfloat16& h, __nv_bfloat16& l) {
    h = __float2bfloat16_rn(x);
    l = __float2bfloat16_rn(x - __bfloat162float(h));
}

// ---------------------------------------------------------------------------
// Conversion kernels
// ---------------------------------------------------------------------------
__global__ __launch_bounds__(256)
void convert_in(const float* __restrict__ q, const float* __restrict__ k,
                const float* __restrict__ v)
{
    const int per = NB * NP * ND / 4;
    int i = blockIdx.x * 256 + threadIdx.x;
    int which = i / per;
    int rem = i - which * per;
    const float* src = (which == 0) ? q : (which == 1) ? k : v;
    float4 x = ((const float4*)src)[rem];
    __nv_bfloat16 h0, h1, h2, h3, l0, l1, l2, l3;
    split1(x.x, h0, l0); split1(x.y, h1, l1);
    split1(x.z, h2, l2); split1(x.w, h3, l3);
    ((uint2*)g_inh)[i] = make_uint2(pack2(h0, h1), pack2(h2, h3));
    ((uint2*)g_inl)[i] = make_uint2(pack2(l0, l1), pack2(l2, l3));
}

__global__ __launch_bounds__(256)
void convert_w(const float* __restrict__ Wq, const float* __restrict__ Wk,
               const float* __restrict__ Wv, const float* __restrict__ Wo)
{
    __shared__ float t[32][33];
    const int mat = blockIdx.z;
    const float* W = (mat == 0) ? Wq : (mat == 1) ? Wk : (mat == 2) ? Wv : Wo;
    const int n0 = blockIdx.x * 32, k0 = blockIdx.y * 32;
    const int tx = threadIdx.x, ty = threadIdx.y;
#pragma unroll
    for (int j = 0; j < 4; j++)
        t[ty + j * 8][tx] = W[(size_t)(k0 + ty + j * 8) * 512 + n0 + tx];
    __syncthreads();
#pragma unroll
    for (int j = 0; j < 4; j++) {
        const int n = n0 + ty + j * 8, kk = k0 + tx;
        float f = t[tx][ty + j * 8];
        __nv_bfloat16 h, l;
        split1(f, h, l);
        const size_t o = (size_t)mat * 262144 + (size_t)n * 512 + kk;
        g_wth[o] = h;
        g_wtl[o] = l;
    }
}

// ---------------------------------------------------------------------------
// bf16x3 GEMM on mma.sync: C[128,128] tile = A[128,512] @ W^T[n,k] + bias.
// K-chunks of 64, cp.async double-buffered. 8 warps (2x4), warp tile 64x32.
// Smem rows: 64 bf16 = 128B + 16B pad = 144B (conflict-free ldmatrix).
// ---------------------------------------------------------------------------
#define ROWB 144
#define ARRB (128 * ROWB)          // 18432 per array
#define STAGEB (4 * ARRB)          // 73728 per stage
#define GEMM_SMEM (2 * STAGEB)     // 147456

__device__ __forceinline__ void load_chunk(
    uint32_t sbase,
    const __nv_bfloat16* __restrict__ Ah, const __nv_bfloat16* __restrict__ Al,
    const __nv_bfloat16* __restrict__ Bh, const __nv_bfloat16* __restrict__ Bl,
    int m0, int n0, int k0, int tid)
{
#pragma unroll 4
    for (int u = tid; u < 4096; u += 256) {
        const int arr = u >> 10, rem = u & 1023;
        const int row = rem >> 3, f4 = rem & 7;
        const __nv_bfloat16* src;
        int gr;
        if (arr == 0)      { src = Ah; gr = m0 + row; }
        else if (arr == 1) { src = Al; gr = m0 + row; }
        else if (arr == 2) { src = Bh; gr = n0 + row; }
        else               { src = Bl; gr = n0 + row; }
        const uint32_t dst = sbase + arr * ARRB + row * ROWB + f4 * 16;
        CP_ASYNC16(dst, src + (size_t)gr * 512 + k0 + f4 * 8);
    }
}

__device__ __forceinline__ void gemm_tc_body(
    const __nv_bfloat16* __restrict__ Ah, const __nv_bfloat16* __restrict__ Al,
    const __nv_bfloat16* __restrict__ Bh, const __nv_bfloat16* __restrict__ Bl,
    const float* __restrict__ bias, float* __restrict__ C,
    int m0, int n0)
{
    extern __shared__ char smbuf[];
    const uint32_t smb = smem_u32(smbuf);
    const int tid = threadIdx.x;
    const int wid = tid >> 5, lane = tid & 31;
    const int warp_m = (wid >> 2) * 64;     // 0 or 64
    const int warp_n = (wid & 3) * 32;      // 0,32,64,96

    float d[4][4][4];
#pragma unroll
    for (int i = 0; i < 4; i++)
#pragma unroll
        for (int j = 0; j < 4; j++)
#pragma unroll
            for (int r = 0; r < 4; r++) d[i][j][r] = 0.f;

    // ldmatrix per-thread address components
    const int a_row = lane & 15, a_kh = (lane >> 4) & 1;          // A: 16 rows x 2 k-halves
    const int b_row = (lane & 7) + ((lane >> 4) & 1) * 8;         // B: 8 rows, 2 n8 tiles
    const int b_kh = (lane >> 3) & 1;

    load_chunk(smb, Ah, Al, Bh, Bl, m0, n0, 0, tid);
    CP_COMMIT();

    for (int c = 0; c < 8; c++) {
        if (c + 1 < 8) {
            load_chunk(smb + ((c + 1) & 1) * STAGEB, Ah, Al, Bh, Bl,
                       m0, n0, (c + 1) * 64, tid);
            CP_COMMIT();
            CP_WAIT(1);
        } else {
            CP_WAIT(0);
        }
        __syncthreads();

        const uint32_t st = smb + (c & 1) * STAGEB;
        const uint32_t sAh = st, sAl = st + ARRB;
        const uint32_t sBh = st + 2 * ARRB, sBl = st + 3 * ARRB;

#pragma unroll
        for (int ks = 0; ks < 4; ks++) {
            const int koff = ks * 32;
            uint32_t ah[4][4], al[4][4], bh[2][4], bl[2][4];
#pragma unroll
            for (int i = 0; i < 4; i++) {
                const uint32_t ao = (warp_m + 16 * i + a_row) * ROWB
                                  + koff + a_kh * 16;
                ldsm_x4(ah[i], sAh + ao);
                ldsm_x4(al[i], sAl + ao);
            }
#pragma unroll
            for (int j = 0; j < 2; j++) {
                const uint32_t bo = (warp_n + 16 * j + b_row) * ROWB
                                  + koff + b_kh * 16;
                ldsm_x4(bh[j], sBh + bo);
                ldsm_x4(bl[j], sBl + bo);
            }
#pragma unroll
            for (int i = 0; i < 4; i++)
#pragma unroll
                for (int j = 0; j < 4; j++) {
                    const uint32_t* ph = &bh[j >> 1][(j & 1) * 2];
                    const uint32_t* pl = &bl[j >> 1][(j & 1) * 2];
                    mma_bf16(d[i][j], ah[i], ph);   // hi*hi
                    mma_bf16(d[i][j], ah[i], pl);   // hi*lo
                    mma_bf16(d[i][j], al[i], ph);   // lo*hi
                }
        }
        __syncthreads();
    }

    // epilogue: c0,c1 at (row, col..col+1), c2,c3 at (row+8, ...)
    const int er = lane >> 2, ec = (lane & 3) * 2;
#pragma unroll
    for (int i = 0; i < 4; i++) {
        const int row = m0 + warp_m + 16 * i + er;
#pragma unroll
        for (int j = 0; j < 4; j++) {
            const int col = n0 + warp_n + 8 * j + ec;
            const float b0 = bias[col], b1 = bias[col + 1];
            *(float2*)(C + (size_t)row * 512 + col) =
                make_float2(d[i][j][0] + b0, d[i][j][1] + b1);
            *(float2*)(C + (size_t)(row + 8) * 512 + col) =
                make_float2(d[i][j][2] + b0, d[i][j][3] + b1);
        }
    }
}

// Projections: grid (4, 32, 3)
__global__ __launch_bounds__(256)
void proj_tc(const float* __restrict__ bq, const float* __restrict__ bk,
             const float* __restrict__ bv)
{
    const int mat = blockIdx.z;
    const size_t aoff = (size_t)mat * (NB * NP * ND);
    const __nv_bfloat16* Bh = g_wth + (size_t)mat * 262144;
    const __nv_bfloat16* Bl = g_wtl + (size_t)mat * 262144;
    const float* bias = (mat == 0) ? bq : (mat == 1) ? bk : bv;
    float* C = (mat == 0) ? g_qp : (mat == 1) ? g_kp : g_vp;
    gemm_tc_body(g_inh + aoff, g_inl + aoff, Bh, Bl, bias, C,
                 blockIdx.y * 128, blockIdx.x * 128);
}

// Output projection: grid (4, 64)
__global__ __launch_bounds__(256)
void out_tc(const float* __restrict__ bo, float* __restrict__ out)
{
    gemm_tc_body(g_cth, g_ctl, g_wth + 3 * 262144, g_wtl + 3 * 262144,
                 bo, out, blockIdx.y * 128, blockIdx.x * 128);
}

// ---------------------------------------------------------------------------
// Band attention (both directions) + A1/A2 full-row stores + bf16 ct epilogue
// ---------------------------------------------------------------------------
#define AST 68
#define ATT_SMEM ((3 * 128 + 2 * 64) * AST * 4)

__global__ __launch_bounds__(256)
void attn_kernel(float* __restrict__ A1out, float* __restrict__ A2out)
{
    extern __shared__ float sm[];
    float* qs = sm;                   // [128][68]
    float* ks = qs + 128 * AST;
    float* vs = ks + 128 * AST;
    float* s1 = vs + 128 * AST;       // [64][68]
    float* s2 = s1 + 64 * AST;

    const int tid = threadIdx.x;
    const int h = blockIdx.y, b = blockIdx.z;
    const int l0g = blockIdx.x * 64;

    for (int i = tid; i < 128 * 16; i += 256) {
        const int r = i >> 4, d4 = (i & 15) * 4;
        const int rg = l0g - 32 + r;
        float4 q4 = make_float4(0.f, 0.f, 0.f, 0.f);
        float4 k4 = q4, v4 = q4;
        if (rg >= 0 && rg < 1024) {
            const size_t base = ((size_t)((b * 1024 + rg) * 8 + h)) * 64 + d4;
            q4 = *(const float4*)(g_qp + base);
            k4 = *(const float4*)(g_kp + base);
            v4 = *(const float4*)(g_vp + base);
        }
        const int o = r * AST + d4;
        *(float4*)(qs + o) = q4;
        *(float4*)(ks + o) = k4;
        *(float4*)(vs + o) = v4;
    }
    __syncthreads();

    // Band scores, 4x4 register tiles.
    for (int t = tid; t < 544; t += 256) {
        const int mat = (t >= 272);
        const int tt = t - (mat ? 272 : 0);
        const int lt = tt / 17, dt = tt - lt * 17;
        const int l0 = lt * 4;
        int ds0 = dt * 4; if (ds0 > 61) ds0 = 61;
        const float* Ar = mat ? ks : qs;
        const float* Bc = mat ? qs : ks;
        float acc[4][4];
#pragma unroll
        for (int i = 0; i < 4; i++)
#pragma unroll
            for (int j = 0; j < 4; j++) acc[i][j] = 0.f;

        for (int e4 = 0; e4 < 16; e4++) {
            float4 a[4], bb[7];
#pragma unroll
            for (int i = 0; i < 4; i++)
                a[i] = *(const float4*)(Ar + (l0 + i + 32) * AST + e4 * 4);
#pragma unroll
            for (int r = 0; r < 7; r++)
                bb[r] = *(const float4*)(Bc + (l0 + ds0 + r) * AST + e4 * 4);
#pragma unroll
            for (int i = 0; i < 4; i++)
#pragma unroll
                for (int j = 0; j < 4; j++) {
                    const float4 bv = bb[i + j];
                    acc[i][j] += a[i].x * bv.x + a[i].y * bv.y
                               + a[i].z * bv.z + a[i].w * bv.w;
                }
        }
        float* S = mat ? s2 : s1;
#pragma unroll
        for (int i = 0; i < 4; i++)
#pragma unroll
            for (int j = 0; j < 4; j++) {
                const int l = l0 + i, ds = ds0 + j;
                const int sg = l0g + l + ds - 32;
                S[l * AST + ds] =
                    (sg >= 0 && sg < 1024) ? 0.125f * acc[i][j] : -1e30f;
            }
    }
    __syncthreads();

    const int warp = tid >> 5, lane = tid & 31;
    for (int task = warp; task < 128; task += 8) {
        float* row = (task < 64) ? (s1 + task * AST) : (s2 + (task - 64) * AST);
        float m = -1e30f;
        for (int ds = lane; ds < 65; ds += 32) m = fmaxf(m, row[ds]);
#pragma unroll
        for (int o = 16; o > 0; o >>= 1) m = fmaxf(m, __shfl_xor_sync(0xffffffffu, m, o));
        float sum = 0.f;
        for (int ds = lane; ds < 65; ds += 32) {
            float pv = __expf(row[ds] - m);
            row[ds] = pv;
            sum += pv;
        }
#pragma unroll
        for (int o = 16; o > 0; o >>= 1) sum += __shfl_xor_sync(0xffffffffu, sum, o);
        const float inv = 1.f / sum;
        for (int ds = lane; ds < 65; ds += 32) row[ds] *= inv;
    }
    __syncthreads();

    // out = A @ V (sliding window V reuse); ct written as bf16 hi/lo.
    for (int task = tid; task < 512; task += 256) {
        const int mat = (task >= 256);
        const int tt = task & 255;
        const int lt = tt >> 4, d4 = (tt & 15) * 4;
        const int l0 = lt * 4;
        const float* S = mat ? s2 : s1;
        const float* V = mat ? qs : vs;
        float4 acc[4];
#pragma unroll
        for (int i = 0; i < 4; i++) acc[i] = make_float4(0.f, 0.f, 0.f, 0.f);
        for (int j = 0; j < 68; j++) {
            const float4 v = *(const float4*)(V + (l0 + j) * AST + d4);
#pragma unroll
            for (int i = 0; i < 4; i++) {
                const int ds = j - i;
                if ((unsigned)ds <= 64u) {
                    const float a = S[(l0 + i) * AST + ds];
                    acc[i].x += a * v.x; acc[i].y += a * v.y;
                    acc[i].z += a * v.z; acc[i].w += a * v.w;
                }
            }
        }
#pragma unroll
        for (int i = 0; i < 4; i++) {
            const int lg = l0g + l0 + i;
            const size_t ci = (((size_t)b * 2048 + (mat ? 1024 : 0) + lg) * 512
                               + h * 64 + d4);
            __nv_bfloat16 h0, h1, h2, h3, lo0, lo1, lo2, lo3;
            split1(acc[i].x, h0, lo0); split1(acc[i].y, h1, lo1);
            split1(acc[i].z, h2, lo2); split1(acc[i].w, h3, lo3);
            *(uint2*)(g_cth + ci) = make_uint2(pack2(h0, h1), pack2(h2, h3));
            *(uint2*)(g_ctl + ci) = make_uint2(pack2(lo0, lo1), pack2(lo2, lo3));
        }
    }

    // Full-width A1/A2 rows (zeros outside band).
    const int s = tid * 4;
    for (int l = 0; l < 64; l++) {
        const int lg = l0g + l;
        const size_t base = (((size_t)(b * 8 + h)) * 1024 + lg) * 1024;
        float4 o1, o2;
        float* p1 = &o1.x;
        float* p2 = &o2.x;
#pragma unroll
        for (int j = 0; j < 4; j++) {
            const int ds = s + j - lg + 32;
            const bool in = (ds >= 0) && (ds <= 64);
            p1[j] = in ? s1[l * AST + ds] : 0.f;
            p2[j] = in ? s2[l * AST + ds] : 0.f;
        }
        *(float4*)(A1out + base + s) = o1;
        *(float4*)(A2out + base + s) = o2;
    }
}

// ---------------------------------------------------------------------------
extern "C" void kernel_launch(void* const* d_in, const int* in_sizes, int n_in,
                              void* d_out, int out_size)
{
    const float* queries = (const float*)d_in[0];
    const float* keys    = (const float*)d_in[1];
    const float* values  = (const float*)d_in[2];
    const float* Wq = (const float*)d_in[3];
    const float* bq = (const float*)d_in[4];
    const float* Wk = (const float*)d_in[5];
    const float* bk = (const float*)d_in[6];
    const float* Wv = (const float*)d_in[7];
    const float* bv = (const float*)d_in[8];
    const float* Wo = (const float*)d_in[9];
    const float* bo = (const float*)d_in[10];

    float* out = (float*)d_out;                         // (4, 2048, 512)
    float* A1  = out + (size_t)4 * 2048 * 512;          // (4, 8, 1024, 1024)
    float* A2  = A1 + (size_t)4 * 8 * 1024 * 1024;      // (4, 8, 1024, 1024)

    cudaFuncSetAttribute(proj_tc, cudaFuncAttributeMaxDynamicSharedMemorySize, GEMM_SMEM);
    cudaFuncSetAttribute(out_tc,  cudaFuncAttributeMaxDynamicSharedMemorySize, GEMM_SMEM);
    cudaFuncSetAttribute(attn_kernel, cudaFuncAttributeMaxDynamicSharedMemorySize, ATT_SMEM);

    // 1) fp32 -> bf16 hi/lo splits
    convert_in<<<3 * NB * NP * ND / 4 / 256, 256>>>(queries, keys, values);
    convert_w<<<dim3(16, 16, 4), dim3(32, 8)>>>(Wq, Wk, Wv, Wo);

    // 2) Q/K/V projections (bf16x3 on HMMA)
    proj_tc<<<dim3(4, 32, 3), 256, GEMM_SMEM>>>(bq, bk, bv);

    // 3) Band attention both directions; writes A1/A2 + bf16 ct
    attn_kernel<<<dim3(16, 8, 4), 256, ATT_SMEM>>>(A1, A2);

    // 4) Output projection (bf16x3 on HMMA)
    out_tc<<<dim3(4, 64), 256, GEMM_SMEM>>>(bo, out);
}

// round 6
// speedup vs baseline: 1.6407x; 1.0262x over previous
#include <cuda_runtime.h>
#include <cuda_bf16.h>
#include <cstdint>
#include <cstring>

#define NB 4
#define NP 1024
#define ND 512
#define NH 8
#define NDK 64

// ---------------------------------------------------------------------------
// Scratch (device globals; no allocations allowed)
// ---------------------------------------------------------------------------
__device__ float g_qp[NB * NP * ND];
__device__ float g_kp[NB * NP * ND];
__device__ float g_vp[NB * NP * ND];
__device__ __align__(16) __nv_bfloat16 g_inh[3 * NB * NP * ND];   // q,k,v hi
__device__ __align__(16) __nv_bfloat16 g_inl[3 * NB * NP * ND];   // q,k,v lo
__device__ __align__(16) __nv_bfloat16 g_wth[4 * ND * ND];        // W^T hi (n,k)
__device__ __align__(16) __nv_bfloat16 g_wtl[4 * ND * ND];        // W^T lo
__device__ __align__(16) __nv_bfloat16 g_cth[NB * 2 * NP * ND];   // concat hi
__device__ __align__(16) __nv_bfloat16 g_ctl[NB * 2 * NP * ND];   // concat lo

// ---------------------------------------------------------------------------
// PTX helpers (sm_100 baseline: mma.sync + ldmatrix + cp.async)
// ---------------------------------------------------------------------------
__device__ __forceinline__ uint32_t smem_u32(const void* p) {
    uint32_t a;
    asm("{ .reg .u64 t; cvta.to.shared.u64 t, %1; cvt.u32.u64 %0, t; }"
        : "=r"(a) : "l"(p));
    return a;
}

#define CP_ASYNC16(dst, src) \
    asm volatile("cp.async.cg.shared.global [%0], [%1], 16;" \
                 :: "r"(dst), "l"(src) : "memory")
#define CP_COMMIT() asm volatile("cp.async.commit_group;" ::: "memory")
#define CP_WAIT(n)  asm volatile("cp.async.wait_group %0;" :: "n"(n) : "memory")

__device__ __forceinline__ void ldsm_x4(uint32_t* r, uint32_t addr) {
    asm volatile("ldmatrix.sync.aligned.m8n8.x4.shared.b16 {%0,%1,%2,%3}, [%4];"
                 : "=r"(r[0]), "=r"(r[1]), "=r"(r[2]), "=r"(r[3]) : "r"(addr));
}

__device__ __forceinline__ void mma_bf16(float* d, const uint32_t* a,
                                         const uint32_t* b) {
    asm volatile(
        "mma.sync.aligned.m16n8k16.row.col.f32.bf16.bf16.f32 "
        "{%0,%1,%2,%3}, {%4,%5,%6,%7}, {%8,%9}, {%0,%1,%2,%3};"
        : "+f"(d[0]), "+f"(d[1]), "+f"(d[2]), "+f"(d[3])
        : "r"(a[0]), "r"(a[1]), "r"(a[2]), "r"(a[3]), "r"(b[0]), "r"(b[1]));
}

__device__ __forceinline__ uint16_t bf_bits(__nv_bfloat16 a) {
    unsigned short s; memcpy(&s, &a, 2); return s;
}
__device__ __forceinline__ uint32_t pack2(__nv_bfloat16 a, __nv_bfloat16 b) {
    return (uint32_t)bf_bits(a) | ((uint32_t)bf_bits(b) << 16);
}
__device__ __forceinline__ void split1(float x, __nv_bfloat16& h, __nv_bfloat16& l) {
    h = __float2bfloat16_rn(x);
    l = __float2bfloat16_rn(x - __bfloat162float(h));
}

// ---------------------------------------------------------------------------
// Conversion kernels
// ---------------------------------------------------------------------------
__global__ __launch_bounds__(256)
void convert_in(const float* __restrict__ q, const float* __restrict__ k,
                const float* __restrict__ v)
{
    const int per = NB * NP * ND / 4;
    int i = blockIdx.x * 256 + threadIdx.x;
    int which = i / per;
    int rem = i - which * per;
    const float* src = (which == 0) ? q : (which == 1) ? k : v;
    float4 x = ((const float4*)src)[rem];
    __nv_bfloat16 h0, h1, h2, h3, l0, l1, l2, l3;
    split1(x.x, h0, l0); split1(x.y, h1, l1);
    split1(x.z, h2, l2); split1(x.w, h3, l3);
    ((uint2*)g_inh)[i] = make_uint2(pack2(h0, h1), pack2(h2, h3));
    ((uint2*)g_inl)[i] = make_uint2(pack2(l0, l1), pack2(l2, l3));
}

__global__ __launch_bounds__(256)
void convert_w(const float* __restrict__ Wq, const float* __restrict__ Wk,
               const float* __restrict__ Wv, const float* __restrict__ Wo)
{
    __shared__ float t[32][33];
    const int mat = blockIdx.z;
    const float* W = (mat == 0) ? Wq : (mat == 1) ? Wk : (mat == 2) ? Wv : Wo;
    const int n0 = blockIdx.x * 32, k0 = blockIdx.y * 32;
    const int tx = threadIdx.x, ty = threadIdx.y;
#pragma unroll
    for (int j = 0; j < 4; j++)
        t[ty + j * 8][tx] = W[(size_t)(k0 + ty + j * 8) * 512 + n0 + tx];
    __syncthreads();
#pragma unroll
    for (int j = 0; j < 4; j++) {
        const int n = n0 + ty + j * 8, kk = k0 + tx;
        float f = t[tx][ty + j * 8];
        __nv_bfloat16 h, l;
        split1(f, h, l);
        const size_t o = (size_t)mat * 262144 + (size_t)n * 512 + kk;
        g_wth[o] = h;
        g_wtl[o] = l;
    }
}

// ---------------------------------------------------------------------------
// bf16x3 GEMM on mma.sync (unchanged from round 3)
// ---------------------------------------------------------------------------
#define ROWB 144
#define ARRB (128 * ROWB)
#define STAGEB (4 * ARRB)
#define GEMM_SMEM (2 * STAGEB)

__device__ __forceinline__ void load_chunk(
    uint32_t sbase,
    const __nv_bfloat16* __restrict__ Ah, const __nv_bfloat16* __restrict__ Al,
    const __nv_bfloat16* __restrict__ Bh, const __nv_bfloat16* __restrict__ Bl,
    int m0, int n0, int k0, int tid)
{
#pragma unroll 4
    for (int u = tid; u < 4096; u += 256) {
        const int arr = u >> 10, rem = u & 1023;
        const int row = rem >> 3, f4 = rem & 7;
        const __nv_bfloat16* src;
        int gr;
        if (arr == 0)      { src = Ah; gr = m0 + row; }
        else if (arr == 1) { src = Al; gr = m0 + row; }
        else if (arr == 2) { src = Bh; gr = n0 + row; }
        else               { src = Bl; gr = n0 + row; }
        const uint32_t dst = sbase + arr * ARRB + row * ROWB + f4 * 16;
        CP_ASYNC16(dst, src + (size_t)gr * 512 + k0 + f4 * 8);
    }
}

__device__ __forceinline__ void gemm_tc_body(
    const __nv_bfloat16* __restrict__ Ah, const __nv_bfloat16* __restrict__ Al,
    const __nv_bfloat16* __restrict__ Bh, const __nv_bfloat16* __restrict__ Bl,
    const float* __restrict__ bias, float* __restrict__ C,
    int m0, int n0)
{
    extern __shared__ char smbuf[];
    const uint32_t smb = smem_u32(smbuf);
    const int tid = threadIdx.x;
    const int wid = tid >> 5, lane = tid & 31;
    const int warp_m = (wid >> 2) * 64;
    const int warp_n = (wid & 3) * 32;

    float d[4][4][4];
#pragma unroll
    for (int i = 0; i < 4; i++)
#pragma unroll
        for (int j = 0; j < 4; j++)
#pragma unroll
            for (int r = 0; r < 4; r++) d[i][j][r] = 0.f;

    const int a_row = lane & 15, a_kh = (lane >> 4) & 1;
    const int b_row = (lane & 7) + ((lane >> 4) & 1) * 8;
    const int b_kh = (lane >> 3) & 1;

    load_chunk(smb, Ah, Al, Bh, Bl, m0, n0, 0, tid);
    CP_COMMIT();

    for (int c = 0; c < 8; c++) {
        if (c + 1 < 8) {
            load_chunk(smb + ((c + 1) & 1) * STAGEB, Ah, Al, Bh, Bl,
                       m0, n0, (c + 1) * 64, tid);
            CP_COMMIT();
            CP_WAIT(1);
        } else {
            CP_WAIT(0);
        }
        __syncthreads();

        const uint32_t st = smb + (c & 1) * STAGEB;
        const uint32_t sAh = st, sAl = st + ARRB;
        const uint32_t sBh = st + 2 * ARRB, sBl = st + 3 * ARRB;

#pragma unroll
        for (int ks = 0; ks < 4; ks++) {
            const int koff = ks * 32;
            uint32_t ah[4][4], al[4][4], bh[2][4], bl[2][4];
#pragma unroll
            for (int i = 0; i < 4; i++) {
                const uint32_t ao = (warp_m + 16 * i + a_row) * ROWB
                                  + koff + a_kh * 16;
                ldsm_x4(ah[i], sAh + ao);
                ldsm_x4(al[i], sAl + ao);
            }
#pragma unroll
            for (int j = 0; j < 2; j++) {
                const uint32_t bo = (warp_n + 16 * j + b_row) * ROWB
                                  + koff + b_kh * 16;
                ldsm_x4(bh[j], sBh + bo);
                ldsm_x4(bl[j], sBl + bo);
            }
#pragma unroll
            for (int i = 0; i < 4; i++)
#pragma unroll
                for (int j = 0; j < 4; j++) {
                    const uint32_t* ph = &bh[j >> 1][(j & 1) * 2];
                    const uint32_t* pl = &bl[j >> 1][(j & 1) * 2];
                    mma_bf16(d[i][j], ah[i], ph);
                    mma_bf16(d[i][j], ah[i], pl);
                    mma_bf16(d[i][j], al[i], ph);
                }
        }
        __syncthreads();
    }

    const int er = lane >> 2, ec = (lane & 3) * 2;
#pragma unroll
    for (int i = 0; i < 4; i++) {
        const int row = m0 + warp_m + 16 * i + er;
#pragma unroll
        for (int j = 0; j < 4; j++) {
            const int col = n0 + warp_n + 8 * j + ec;
            const float b0 = bias[col], b1 = bias[col + 1];
            *(float2*)(C + (size_t)row * 512 + col) =
                make_float2(d[i][j][0] + b0, d[i][j][1] + b1);
            *(float2*)(C + (size_t)(row + 8) * 512 + col) =
                make_float2(d[i][j][2] + b0, d[i][j][3] + b1);
        }
    }
}

__global__ __launch_bounds__(256)
void proj_tc(const float* __restrict__ bq, const float* __restrict__ bk,
             const float* __restrict__ bv)
{
    const int mat = blockIdx.z;
    const size_t aoff = (size_t)mat * (NB * NP * ND);
    const __nv_bfloat16* Bh = g_wth + (size_t)mat * 262144;
    const __nv_bfloat16* Bl = g_wtl + (size_t)mat * 262144;
    const float* bias = (mat == 0) ? bq : (mat == 1) ? bk : bv;
    float* C = (mat == 0) ? g_qp : (mat == 1) ? g_kp : g_vp;
    gemm_tc_body(g_inh + aoff, g_inl + aoff, Bh, Bl, bias, C,
                 blockIdx.y * 128, blockIdx.x * 128);
}

__global__ __launch_bounds__(256)
void out_tc(const float* __restrict__ bo, float* __restrict__ out)
{
    gemm_tc_body(g_cth, g_ctl, g_wth + 3 * 262144, g_wtl + 3 * 262144,
                 bo, out, blockIdx.y * 128, blockIdx.x * 128);
}

// ---------------------------------------------------------------------------
// Band attention v2: 512 threads, zero-store phase hoisted to front,
// compact band-value stores after softmax. Streaming stores for A1/A2.
// ---------------------------------------------------------------------------
#define AST 68
#define ATT_SMEM ((3 * 128 + 2 * 64) * AST * 4)
#define ATT_THREADS 512

__global__ __launch_bounds__(ATT_THREADS)
void attn_kernel(float* __restrict__ A1out, float* __restrict__ A2out)
{
    extern __shared__ float sm[];
    float* qs = sm;                   // [128][68]
    float* ks = qs + 128 * AST;
    float* vs = ks + 128 * AST;
    float* s1 = vs + 128 * AST;       // [64][68]
    float* s2 = s1 + 64 * AST;

    const int tid = threadIdx.x;
    const int h = blockIdx.y, b = blockIdx.z;
    const int l0g = blockIdx.x * 64;
    const size_t arow0 = (((size_t)(b * 8 + h)) * 1024 + l0g) * 1024;

    // Phase 0: zero the full 64x1024 A1/A2 row blocks (band overwritten later).
    // Pure streaming STG issued before any dependency so DRAM drains during
    // compute; __stcs keeps the write-once data from polluting L2.
    {
        const float4 z = make_float4(0.f, 0.f, 0.f, 0.f);
        float4* z1 = (float4*)(A1out + arow0);
        float4* z2 = (float4*)(A2out + arow0);
        for (int i = tid; i < 16384; i += ATT_THREADS) {
            __stcs(z1 + i, z);
            __stcs(z2 + i, z);
        }
    }

    // Load q/k/v tiles: rows l0g-32 .. l0g+95 (zero pad OOR)
    for (int i = tid; i < 128 * 16; i += ATT_THREADS) {
        const int r = i >> 4, d4 = (i & 15) * 4;
        const int rg = l0g - 32 + r;
        float4 q4 = make_float4(0.f, 0.f, 0.f, 0.f);
        float4 k4 = q4, v4 = q4;
        if (rg >= 0 && rg < 1024) {
            const size_t base = ((size_t)((b * 1024 + rg) * 8 + h)) * 64 + d4;
            q4 = *(const float4*)(g_qp + base);
            k4 = *(const float4*)(g_kp + base);
            v4 = *(const float4*)(g_vp + base);
        }
        const int o = r * AST + d4;
        *(float4*)(qs + o) = q4;
        *(float4*)(ks + o) = k4;
        *(float4*)(vs + o) = v4;
    }
    __syncthreads();

    // Band scores, 4x4 register tiles.
    for (int t = tid; t < 544; t += ATT_THREADS) {
        const int mat = (t >= 272);
        const int tt = t - (mat ? 272 : 0);
        const int lt = tt / 17, dt = tt - lt * 17;
        const int l0 = lt * 4;
        int ds0 = dt * 4; if (ds0 > 61) ds0 = 61;
        const float* Ar = mat ? ks : qs;
        const float* Bc = mat ? qs : ks;
        float acc[4][4];
#pragma unroll
        for (int i = 0; i < 4; i++)
#pragma unroll
            for (int j = 0; j < 4; j++) acc[i][j] = 0.f;

        for (int e4 = 0; e4 < 16; e4++) {
            float4 a[4], bb[7];
#pragma unroll
            for (int i = 0; i < 4; i++)
                a[i] = *(const float4*)(Ar + (l0 + i + 32) * AST + e4 * 4);
#pragma unroll
            for (int r = 0; r < 7; r++)
                bb[r] = *(const float4*)(Bc + (l0 + ds0 + r) * AST + e4 * 4);
#pragma unroll
            for (int i = 0; i < 4; i++)
#pragma unroll
                for (int j = 0; j < 4; j++) {
                    const float4 bv = bb[i + j];
                    acc[i][j] += a[i].x * bv.x + a[i].y * bv.y
                               + a[i].z * bv.z + a[i].w * bv.w;
                }
        }
        float* S = mat ? s2 : s1;
#pragma unroll
        for (int i = 0; i < 4; i++)
#pragma unroll
            for (int j = 0; j < 4; j++) {
                const int l = l0 + i, ds = ds0 + j;
                const int sg = l0g + l + ds - 32;
                S[l * AST + ds] =
                    (sg >= 0 && sg < 1024) ? 0.125f * acc[i][j] : -1e30f;
            }
    }
    __syncthreads();

    // Row softmax: 128 tasks, warp per task, 16 warps.
    const int warp = tid >> 5, lane = tid & 31;
    for (int task = warp; task < 128; task += ATT_THREADS / 32) {
        float* row = (task < 64) ? (s1 + task * AST) : (s2 + (task - 64) * AST);
        float m = -1e30f;
        for (int ds = lane; ds < 65; ds += 32) m = fmaxf(m, row[ds]);
#pragma unroll
        for (int o = 16; o > 0; o >>= 1) m = fmaxf(m, __shfl_xor_sync(0xffffffffu, m, o));
        float sum = 0.f;
        for (int ds = lane; ds < 65; ds += 32) {
            float pv = __expf(row[ds] - m);
            row[ds] = pv;
            sum += pv;
        }
#pragma unroll
        for (int o = 16; o > 0; o >>= 1) sum += __shfl_xor_sync(0xffffffffu, sum, o);
        const float inv = 1.f / sum;
        for (int ds = lane; ds < 65; ds += 32) row[ds] *= inv;
    }
    __syncthreads();

    // Band value stores: 2 mats x 64 rows x 65 cols (overwrites zeros in band).
    for (int t = tid; t < 8320; t += ATT_THREADS) {
        const int mat = (t >= 4160);
        const int rem = t - (mat ? 4160 : 0);
        const int l = rem / 65, j = rem - l * 65;
        const int lg = l0g + l;
        const int col = lg + j - 32;
        if (col >= 0 && col < 1024) {
            float* dst = (mat ? A2out : A1out) + arow0 + (size_t)l * 1024 + col;
            const float* S = mat ? s2 : s1;
            __stcs(dst, S[l * AST + j]);
        }
    }

    // out = A @ V (sliding window V reuse); ct written as bf16 hi/lo.
    for (int task = tid; task < 512; task += ATT_THREADS) {
        const int mat = (task >= 256);
        const int tt = task & 255;
        const int lt = tt >> 4, d4 = (tt & 15) * 4;
        const int l0 = lt * 4;
        const float* S = mat ? s2 : s1;
        const float* V = mat ? qs : vs;
        float4 acc[4];
#pragma unroll
        for (int i = 0; i < 4; i++) acc[i] = make_float4(0.f, 0.f, 0.f, 0.f);
        for (int j = 0; j < 68; j++) {
            const float4 v = *(const float4*)(V + (l0 + j) * AST + d4);
#pragma unroll
            for (int i = 0; i < 4; i++) {
                const int ds = j - i;
                if ((unsigned)ds <= 64u) {
                    const float a = S[(l0 + i) * AST + ds];
                    acc[i].x += a * v.x; acc[i].y += a * v.y;
                    acc[i].z += a * v.z; acc[i].w += a * v.w;
                }
            }
        }
#pragma unroll
        for (int i = 0; i < 4; i++) {
            const int lg = l0g + l0 + i;
            const size_t ci = (((size_t)b * 2048 + (mat ? 1024 : 0) + lg) * 512
                               + h * 64 + d4);
            __nv_bfloat16 h0, h1, h2, h3, lo0, lo1, lo2, lo3;
            split1(acc[i].x, h0, lo0); split1(acc[i].y, h1, lo1);
            split1(acc[i].z, h2, lo2); split1(acc[i].w, h3, lo3);
            *(uint2*)(g_cth + ci) = make_uint2(pack2(h0, h1), pack2(h2, h3));
            *(uint2*)(g_ctl + ci) = make_uint2(pack2(lo0, lo1), pack2(lo2, lo3));
        }
    }
}

// ---------------------------------------------------------------------------
extern "C" void kernel_launch(void* const* d_in, const int* in_sizes, int n_in,
                              void* d_out, int out_size)
{
    const float* queries = (const float*)d_in[0];
    const float* keys    = (const float*)d_in[1];
    const float* values  = (const float*)d_in[2];
    const float* Wq = (const float*)d_in[3];
    const float* bq = (const float*)d_in[4];
    const float* Wk = (const float*)d_in[5];
    const float* bk = (const float*)d_in[6];
    const float* Wv = (const float*)d_in[7];
    const float* bv = (const float*)d_in[8];
    const float* Wo = (const float*)d_in[9];
    const float* bo = (const float*)d_in[10];

    float* out = (float*)d_out;                         // (4, 2048, 512)
    float* A1  = out + (size_t)4 * 2048 * 512;          // (4, 8, 1024, 1024)
    float* A2  = A1 + (size_t)4 * 8 * 1024 * 1024;      // (4, 8, 1024, 1024)

    cudaFuncSetAttribute(proj_tc, cudaFuncAttributeMaxDynamicSharedMemorySize, GEMM_SMEM);
    cudaFuncSetAttribute(out_tc,  cudaFuncAttributeMaxDynamicSharedMemorySize, GEMM_SMEM);
    cudaFuncSetAttribute(attn_kernel, cudaFuncAttributeMaxDynamicSharedMemorySize, ATT_SMEM);

    // 1) fp32 -> bf16 hi/lo splits
    convert_in<<<3 * NB * NP * ND / 4 / 256, 256>>>(queries, keys, values);
    convert_w<<<dim3(16, 16, 4), dim3(32, 8)>>>(Wq, Wk, Wv, Wo);

    // 2) Q/K/V projections (bf16x3 on HMMA)
    proj_tc<<<dim3(4, 32, 3), 256, GEMM_SMEM>>>(bq, bk, bv);

    // 3) Band attention both directions; zero+band A1/A2 stores + bf16 ct
    attn_kernel<<<dim3(16, 8, 4), ATT_THREADS, ATT_SMEM>>>(A1, A2);

    // 4) Output projection (bf16x3 on HMMA)
    out_tc<<<dim3(4, 64), 256, GEMM_SMEM>>>(bo, out);
}